// round 11
// baseline (speedup 1.0000x reference)
#include <cuda_runtime.h>
#include <cstdint>
#include <cstddef>

#define BATCHES 16
#define NPTS    65536
#define NSAMP   2048
#define CPB     8                    // CTAs per batch = cluster size
#define NPC     (NPTS / CPB)         // 8192 points per CTA
#define THREADS 512
#define NWARPS  (THREADS / 32)       // 16
#define PPT     (NPC / THREADS)      // 16 consecutive points per thread

// dynamic smem: local copy of this CTA's coords (winner lookup only)
#define SMEM_BYTES (3 * NPC * 4)     // 96 KB

// Reference-matching (XLA-contracted) squared distance:
// d = fma(dz,dz, fma(dy,dy, dx*dx)).  Bit-identical to passing R8-R10 kernels.
static __device__ __forceinline__ float sqdist_ref(float dx, float dy, float dz) {
    return __fmaf_rn(dz, dz, __fmaf_rn(dy, dy, __fmul_rn(dx, dx)));
}

static __device__ __forceinline__ unsigned cluster_rank_() {
    unsigned r;
    asm("mov.u32 %0, %%cluster_ctarank;" : "=r"(r));
    return r;
}
static __device__ __forceinline__ unsigned mapa_shared_(unsigned addr, unsigned target) {
    unsigned r;
    asm("mapa.shared::cluster.u32 %0, %1, %2;" : "=r"(r) : "r"(addr), "r"(target));
    return r;
}
static __device__ __forceinline__ void st_cluster_v4_(unsigned addr, unsigned a, unsigned b,
                                                      unsigned c, unsigned d) {
    asm volatile("st.shared::cluster.v4.b32 [%0], {%1,%2,%3,%4};"
                 :: "r"(addr), "r"(a), "r"(b), "r"(c), "r"(d) : "memory");
}
static __device__ __forceinline__ void st_cluster_b32_(unsigned addr, unsigned a) {
    asm volatile("st.shared::cluster.b32 [%0], %1;"
                 :: "r"(addr), "r"(a) : "memory");
}
static __device__ __forceinline__ void cluster_sync_() {
    asm volatile("barrier.cluster.arrive.aligned;" ::: "memory");
    asm volatile("barrier.cluster.wait.aligned;" ::: "memory");
}
static __device__ __forceinline__ void mbar_init_(unsigned addr, unsigned count) {
    asm volatile("mbarrier.init.shared.b64 [%0], %1;" :: "r"(addr), "r"(count) : "memory");
}
// Arrive (release, cluster scope) on a possibly-remote CTA's mbarrier.
static __device__ __forceinline__ void mbar_arrive_remote_(unsigned remote_addr) {
    asm volatile("mbarrier.arrive.release.cluster.shared::cluster.b64 _, [%0];"
                 :: "r"(remote_addr) : "memory");
}
// Wait (acquire, cluster scope) on the local mbarrier for a phase parity.
static __device__ __forceinline__ void mbar_wait_cluster_(unsigned mbar, unsigned parity) {
    unsigned done;
    asm volatile(
        "{\n\t.reg .pred P;\n\t"
        "mbarrier.try_wait.parity.acquire.cluster.shared::cta.b64 P, [%1], %2;\n\t"
        "selp.b32 %0, 1, 0, P;\n\t}"
        : "=r"(done) : "r"(mbar), "r"(parity) : "memory");
    while (!done) {
        asm volatile(
            "{\n\t.reg .pred P;\n\t"
            "mbarrier.try_wait.parity.acquire.cluster.shared::cta.b64 P, [%1], %2, 0x989680;\n\t"
            "selp.b32 %0, 1, 0, P;\n\t}"
            : "=r"(done) : "r"(mbar), "r"(parity) : "memory");
    }
}

__global__ void __launch_bounds__(THREADS, 1) __cluster_dims__(CPB, 1, 1)
fps_kernel(const float* __restrict__ t_in, float* __restrict__ out)
{
    extern __shared__ float sm[];
    float* spx = sm;
    float* spy = sm + NPC;
    float* spz = sm + 2 * NPC;

    // Double-buffered cluster slot exchange + mbarriers (one arrive per source CTA).
    __shared__ __align__(16) float s_slots[2][CPB][8];
    __shared__ __align__(8)  unsigned long long s_mbar[2];
    __shared__ unsigned s_v[NWARPS];
    __shared__ unsigned s_i[NWARPS];

    const int tid  = threadIdx.x;
    const int lane = tid & 31;
    const int warp = tid >> 5;
    const unsigned rank = cluster_rank_();
    const int batch = blockIdx.x / CPB;

    const float* __restrict__ pb = t_in + (size_t)batch * ((size_t)NPTS * 3);

    const unsigned slots_u32 = (unsigned)__cvta_generic_to_shared(&s_slots[0][0][0]);
    const unsigned mbar_u32  = (unsigned)__cvta_generic_to_shared(&s_mbar[0]);

    if (tid == 0) {
        mbar_init_(mbar_u32,     CPB);   // buffer 0
        mbar_init_(mbar_u32 + 8, CPB);   // buffer 1
    }
    __syncthreads();

    // ---- load my 16 consecutive points into registers + smem copy ----
    const int base = (int)rank * NPC + tid * PPT;   // within-batch global index
    float px[PPT], py[PPT], pz[PPT], dist[PPT];
    {
        const float4* p4 = (const float4*)(pb + (size_t)base * 3);  // 192B aligned
        float c[PPT * 3];
        #pragma unroll
        for (int q = 0; q < (PPT * 3) / 4; q++) {
            float4 v = __ldg(p4 + q);
            c[4 * q + 0] = v.x; c[4 * q + 1] = v.y;
            c[4 * q + 2] = v.z; c[4 * q + 3] = v.w;
        }
        #pragma unroll
        for (int j = 0; j < PPT; j++) {
            px[j] = c[3 * j]; py[j] = c[3 * j + 1]; pz[j] = c[3 * j + 2];
            dist[j] = 1e10f;
            int li = tid * PPT + j;
            spx[li] = px[j]; spy[li] = py[j]; spz[li] = pz[j];
        }
    }

    // First sample is always index 0; its coords seed the loop.
    float lx = __ldg(pb + 0), ly = __ldg(pb + 1), lz = __ldg(pb + 2);
    if (rank == 0 && tid == 0) out[batch * NSAMP] = 0.0f;

    // All CTAs' mbarriers must be initialized before any remote arrive.
    __syncthreads();
    cluster_sync_();

    unsigned phase[2] = {0u, 0u};    // per-thread wait parity per buffer

    for (int k = 1; k < NSAMP; k++) {
        // ---- register-resident distance update + per-thread first-max ----
        float bestv = -1.0f;
        int   bestj = 0;
        #pragma unroll
        for (int j = 0; j < PPT; j++) {
            float d  = sqdist_ref(px[j] - lx, py[j] - ly, pz[j] - lz);
            float nd = fminf(dist[j], d);
            dist[j] = nd;
            if (nd > bestv) { bestv = nd; bestj = j; }  // strict >: first max (asc. j)
        }
        unsigned vb   = __float_as_uint(bestv);         // dist>=0: uint order == float order
        int      gidx = base + bestj;

        // ---- warp argmax: redux + ballot + ffs (lowest lane == lowest index) ----
        unsigned vmax = __reduce_max_sync(0xffffffffu, vb);
        unsigned eq   = __ballot_sync(0xffffffffu, vb == vmax);
        int      src  = __ffs(eq) - 1;
        int      widx = __shfl_sync(0xffffffffu, gidx, src);
        if (lane == 0) { s_v[warp] = vmax; s_i[warp] = (unsigned)widx; }
        __syncthreads();

        const unsigned b = (unsigned)(k & 1);

        // ---- warp 0: CTA argmax, push slot + arrive on all 8 CTAs ----
        if (warp == 0) {
            unsigned v  = (lane < NWARPS) ? s_v[lane] : 0u;   // warps asc == index asc
            unsigned vm = __reduce_max_sync(0xffffffffu, v);
            unsigned e2 = __ballot_sync(0xffffffffu, v == vm);
            int      s2 = __ffs(e2) - 1;
            unsigned cidx = s_i[s2];                          // CTA winner index

            if (lane < CPB) {
                int li = (int)cidx - (int)rank * NPC;         // winner is CTA-local
                unsigned xb = __float_as_uint(spx[li]);
                unsigned yb = __float_as_uint(spy[li]);
                unsigned zb = __float_as_uint(spz[li]);
                unsigned la = slots_u32 + ((b * CPB + rank) * 8u) * 4u;
                unsigned ra = mapa_shared_(la, (unsigned)lane);
                st_cluster_v4_(ra, vm, __float_as_uint(__uint2float_rn(cidx)), xb, yb);
                st_cluster_b32_(ra + 16u, zb);
                // release-arrive on target CTA's mbarrier orders the stores above
                unsigned rm = mapa_shared_(mbar_u32 + b * 8u, (unsigned)lane);
                mbar_arrive_remote_(rm);
            }
        }

        // ---- all threads wait for 8 arrivals on the LOCAL mbarrier ----
        mbar_wait_cluster_(mbar_u32 + b * 8u, phase[b]);
        phase[b] ^= 1u;

        // ---- every thread scans the 8 local slots for the batch winner ----
        const float* ss = &s_slots[b][0][0];
        unsigned bb = 0u;
        int      bs = 0;
        #pragma unroll
        for (int s = 0; s < CPB; s++) {
            unsigned v = __float_as_uint(ss[s * 8]);
            if (v > bb) { bb = v; bs = s; }                   // strict >: lowest rank wins tie
        }
        const float* w = ss + bs * 8;
        lx = w[2]; ly = w[3]; lz = w[4];

        if (rank == 0 && tid == 0) out[batch * NSAMP + k] = w[1];
    }
}

extern "C" void kernel_launch(void* const* d_in, const int* in_sizes, int n_in,
                              void* d_out, int out_size)
{
    // t_in is the largest input under any size convention.
    int best = 0;
    for (int i = 1; i < n_in; i++)
        if (in_sizes[i] > in_sizes[best]) best = i;
    const float* t_in = (const float*)d_in[best];

    // Not a stream op; graph-capture safe.
    cudaFuncSetAttribute(fps_kernel, cudaFuncAttributeMaxDynamicSharedMemorySize,
                         SMEM_BYTES);

    fps_kernel<<<BATCHES * CPB, THREADS, SMEM_BYTES>>>(t_in, (float*)d_out);
}

// round 12
// speedup vs baseline: 1.0364x; 1.0364x over previous
#include <cuda_runtime.h>
#include <cstdint>
#include <cstddef>

#define BATCHES 16
#define NPTS    65536
#define NSAMP   2048
#define CPB     8                    // CTAs per batch = cluster size
#define NPC     (NPTS / CPB)         // 8192 points per CTA
#define THREADS 512
#define NWARPS  (THREADS / 32)       // 16
#define PPT     (NPC / THREADS)      // 16 consecutive points per thread
#define NPAIR   (PPT / 2)            // 8 packed point-pairs per thread

// dynamic smem: local copy of this CTA's coords (winner lookup only)
#define SMEM_BYTES (3 * NPC * 4)     // 96 KB

typedef unsigned long long u64;

// ---- packed f32x2 helpers (per-lane IEEE .rn — bit-identical to scalar) ----
static __device__ __forceinline__ u64 pack2_(float lo, float hi) {
    u64 r; asm("mov.b64 %0, {%1, %2};" : "=l"(r) : "f"(lo), "f"(hi)); return r;
}
static __device__ __forceinline__ void unpack2_(u64 v, float& lo, float& hi) {
    asm("mov.b64 {%0, %1}, %2;" : "=f"(lo), "=f"(hi) : "l"(v));
}
static __device__ __forceinline__ u64 add2_(u64 a, u64 b) {
    u64 r; asm("add.rn.f32x2 %0, %1, %2;" : "=l"(r) : "l"(a), "l"(b)); return r;
}
static __device__ __forceinline__ u64 mul2_(u64 a, u64 b) {
    u64 r; asm("mul.rn.f32x2 %0, %1, %2;" : "=l"(r) : "l"(a), "l"(b)); return r;
}
static __device__ __forceinline__ u64 fma2_(u64 a, u64 b, u64 c) {
    u64 r; asm("fma.rn.f32x2 %0, %1, %2, %3;" : "=l"(r) : "l"(a), "l"(b), "l"(c)); return r;
}

static __device__ __forceinline__ unsigned cluster_rank_() {
    unsigned r;
    asm("mov.u32 %0, %%cluster_ctarank;" : "=r"(r));
    return r;
}
static __device__ __forceinline__ unsigned mapa_shared_(unsigned addr, unsigned target) {
    unsigned r;
    asm("mapa.shared::cluster.u32 %0, %1, %2;" : "=r"(r) : "r"(addr), "r"(target));
    return r;
}
static __device__ __forceinline__ void st_cluster_v4_(unsigned addr, unsigned a, unsigned b,
                                                      unsigned c, unsigned d) {
    asm volatile("st.shared::cluster.v4.b32 [%0], {%1,%2,%3,%4};"
                 :: "r"(addr), "r"(a), "r"(b), "r"(c), "r"(d) : "memory");
}
static __device__ __forceinline__ void st_cluster_b32_(unsigned addr, unsigned a) {
    asm volatile("st.shared::cluster.b32 [%0], %1;"
                 :: "r"(addr), "r"(a) : "memory");
}
static __device__ __forceinline__ void cluster_sync_() {
    asm volatile("barrier.cluster.arrive.aligned;" ::: "memory");
    asm volatile("barrier.cluster.wait.aligned;" ::: "memory");
}

__global__ void __launch_bounds__(THREADS, 1) __cluster_dims__(CPB, 1, 1)
fps_kernel(const float* __restrict__ t_in, float* __restrict__ out)
{
    extern __shared__ float sm[];
    float* spx = sm;
    float* spy = sm + NPC;
    float* spz = sm + 2 * NPC;

    // Double-buffered cluster slot exchange: [buf][src_rank][8] = {val, idx, x, y, z,...}
    __shared__ __align__(16) float s_slots[2][CPB][8];
    __shared__ unsigned s_v[NWARPS];
    __shared__ unsigned s_i[NWARPS];

    const int tid  = threadIdx.x;
    const int lane = tid & 31;
    const int warp = tid >> 5;
    const unsigned rank = cluster_rank_();
    const int batch = blockIdx.x / CPB;

    const float* __restrict__ pb = t_in + (size_t)batch * ((size_t)NPTS * 3);

    // ---- load my 16 consecutive points into packed register pairs + smem copy ----
    const int base = (int)rank * NPC + tid * PPT;   // within-batch global index
    u64 px2[NPAIR], py2[NPAIR], pz2[NPAIR];
    float dist[PPT];
    {
        const float4* p4 = (const float4*)(pb + (size_t)base * 3);  // 192B aligned
        float c[PPT * 3];
        #pragma unroll
        for (int q = 0; q < (PPT * 3) / 4; q++) {
            float4 v = __ldg(p4 + q);
            c[4 * q + 0] = v.x; c[4 * q + 1] = v.y;
            c[4 * q + 2] = v.z; c[4 * q + 3] = v.w;
        }
        #pragma unroll
        for (int q = 0; q < NPAIR; q++) {
            px2[q] = pack2_(c[6 * q + 0], c[6 * q + 3]);
            py2[q] = pack2_(c[6 * q + 1], c[6 * q + 4]);
            pz2[q] = pack2_(c[6 * q + 2], c[6 * q + 5]);
        }
        #pragma unroll
        for (int j = 0; j < PPT; j++) {
            dist[j] = 1e10f;
            int li = tid * PPT + j;
            spx[li] = c[3 * j]; spy[li] = c[3 * j + 1]; spz[li] = c[3 * j + 2];
        }
    }

    // First sample is always index 0; its coords seed the loop.
    float lx = __ldg(pb + 0), ly = __ldg(pb + 1), lz = __ldg(pb + 2);
    if (rank == 0 && tid == 0) out[batch * NSAMP] = 0.0f;
    __syncthreads();

    const unsigned slots_u32 =
        (unsigned)__cvta_generic_to_shared(&s_slots[0][0][0]);

    for (int k = 1; k < NSAMP; k++) {
        // ---- packed distance update: 2 points per instruction ----
        // x - l  ==  x + (-l) exactly (IEEE), so pre-negate and use add.rn.f32x2.
        const u64 nlx = pack2_(-lx, -lx);
        const u64 nly = pack2_(-ly, -ly);
        const u64 nlz = pack2_(-lz, -lz);

        float bestv = -1.0f;
        int   bestj = 0;
        #pragma unroll
        for (int q = 0; q < NPAIR; q++) {
            u64 dx2 = add2_(px2[q], nlx);
            u64 dy2 = add2_(py2[q], nly);
            u64 dz2 = add2_(pz2[q], nlz);
            // d = fma(dz,dz, fma(dy,dy, dx*dx)) per lane — bit-identical to ref.
            u64 d2  = fma2_(dz2, dz2, fma2_(dy2, dy2, mul2_(dx2, dx2)));
            float dlo, dhi;
            unpack2_(d2, dlo, dhi);
            float n0 = fminf(dist[2 * q + 0], dlo); dist[2 * q + 0] = n0;
            float n1 = fminf(dist[2 * q + 1], dhi); dist[2 * q + 1] = n1;
            if (n0 > bestv) { bestv = n0; bestj = 2 * q + 0; }  // strict >: first max
            if (n1 > bestv) { bestv = n1; bestj = 2 * q + 1; }
        }
        unsigned vb   = __float_as_uint(bestv);         // dist>=0: uint order == float order
        int      gidx = base + bestj;

        // ---- warp argmax: redux + ballot + ffs (lowest lane == lowest index) ----
        unsigned vmax = __reduce_max_sync(0xffffffffu, vb);
        unsigned eq   = __ballot_sync(0xffffffffu, vb == vmax);
        int      src  = __ffs(eq) - 1;
        int      widx = __shfl_sync(0xffffffffu, gidx, src);
        if (lane == 0) { s_v[warp] = vmax; s_i[warp] = (unsigned)widx; }
        __syncthreads();

        // ---- warp 0: CTA argmax, push winner slot into all 8 CTAs' smem ----
        if (warp == 0) {
            unsigned v  = (lane < NWARPS) ? s_v[lane] : 0u;   // warps asc == index asc
            unsigned vm = __reduce_max_sync(0xffffffffu, v);
            unsigned e2 = __ballot_sync(0xffffffffu, v == vm);
            int      s2 = __ffs(e2) - 1;
            unsigned cidx = s_i[s2];                          // CTA winner index

            if (lane < CPB) {
                int li = (int)cidx - (int)rank * NPC;         // winner is CTA-local
                unsigned xb = __float_as_uint(spx[li]);
                unsigned yb = __float_as_uint(spy[li]);
                unsigned zb = __float_as_uint(spz[li]);
                unsigned la = slots_u32 + (((unsigned)(k & 1) * CPB + rank) * 8u) * 4u;
                unsigned ra = mapa_shared_(la, (unsigned)lane);
                st_cluster_v4_(ra, vm, __float_as_uint(__uint2float_rn(cidx)), xb, yb);
                st_cluster_b32_(ra + 16u, zb);
            }
        }
        // barrier.cluster: arrive releases the DSMEM stores, wait acquires them.
        cluster_sync_();

        // ---- every thread scans the 8 local slots for the batch winner ----
        const float* ss = &s_slots[k & 1][0][0];
        unsigned bb = 0u;
        int      bs = 0;
        #pragma unroll
        for (int s = 0; s < CPB; s++) {
            unsigned v = __float_as_uint(ss[s * 8]);
            if (v > bb) { bb = v; bs = s; }                   // strict >: lowest rank wins tie
        }
        const float* w = ss + bs * 8;
        lx = w[2]; ly = w[3]; lz = w[4];

        if (rank == 0 && tid == 0) out[batch * NSAMP + k] = w[1];
    }
}

extern "C" void kernel_launch(void* const* d_in, const int* in_sizes, int n_in,
                              void* d_out, int out_size)
{
    // t_in is the largest input under any size convention.
    int best = 0;
    for (int i = 1; i < n_in; i++)
        if (in_sizes[i] > in_sizes[best]) best = i;
    const float* t_in = (const float*)d_in[best];

    // Not a stream op; graph-capture safe.
    cudaFuncSetAttribute(fps_kernel, cudaFuncAttributeMaxDynamicSharedMemorySize,
                         SMEM_BYTES);

    fps_kernel<<<BATCHES * CPB, THREADS, SMEM_BYTES>>>(t_in, (float*)d_out);
}